// round 3
// baseline (speedup 1.0000x reference)
#include <cuda_runtime.h>
#include <stdint.h>
#include <math.h>

// VectorQuantizerGumbel — fused single-pass (flash-style) fp32 kernel.
// Outputs (flattened, float32): z_q_st [16384*256], total_loss [1], codes [16384].

#define NROWS   16384
#define NCODES  8192
#define DIM     256
#define BR      64          // rows per CTA
#define KT      64          // codes per tile
#define NZ      (NROWS*DIM) // 4194304
#define CS_PITCH 257        // odd pitch -> conflict-free strided column reads
#define SS_PITCH 66
#define NBLK    (NROWS/BR)  // 256
#define NTILE   (NCODES/KT) // 128
#define LOGK    9.0109133f  // ln(8192)

__device__ float g_commitPart[NBLK];
__device__ float g_klPart[NBLK];

// ---------------- threefry2x32, key = (0, 42)  (jax.random.key(42)) -------
__device__ __forceinline__ uint32_t tf_rotl(uint32_t x, int d) {
    return __funnelshift_l(x, x, d);
}

__device__ __forceinline__ uint2 threefry_0_42(uint32_t x0, uint32_t x1) {
    const uint32_t ks0 = 0u, ks1 = 42u, ks2 = 0u ^ 42u ^ 0x1BD11BDAu;
    x0 += ks0; x1 += ks1;
#define TFR(R) { x0 += x1; x1 = tf_rotl(x1,(R)); x1 ^= x0; }
    TFR(13) TFR(15) TFR(26) TFR(6)
    x0 += ks1; x1 += ks2 + 1u;
    TFR(17) TFR(29) TFR(16) TFR(24)
    x0 += ks2; x1 += ks0 + 2u;
    TFR(13) TFR(15) TFR(26) TFR(6)
    x0 += ks0; x1 += ks1 + 3u;
    TFR(17) TFR(29) TFR(16) TFR(24)
    x0 += ks1; x1 += ks2 + 4u;
    TFR(13) TFR(15) TFR(26) TFR(6)
    x0 += ks2; x1 += ks0 + 5u;
#undef TFR
    return make_uint2(x0, x1);
}

__device__ __forceinline__ float gumbel_from_bits(uint32_t b) {
    // JAX uniform: f = bitcast(bits>>9 | 1.0f_bits) - 1 ; u = max(tiny, f)
    float f = __uint_as_float((b >> 9) | 0x3f800000u) - 1.0f;
    float u = fmaxf(f, 1.17549435e-38f);
    float w = -logf(u);          // accurate log: u near 1 -> tiny w, must be precise
    return -__logf(w);           // outer log: fast version is fine
}

// jax_threefry_partitionable=True (default in modern JAX):
// counter = uint64 flat index -> (x0, x1) = (hi32, lo32); 32-bit draw = out.x ^ out.y
__device__ __forceinline__ float gumbel_rc(uint32_t r, uint32_t c) {
    uint32_t m = r * (uint32_t)NCODES + c;   // flat index into (16384, 8192), < 2^27
    uint2 o = threefry_0_42(0u, m);
    return gumbel_from_bits(o.x ^ o.y);
}

// ---------------- 16-lane butterfly reductions ----------------------------
__device__ __forceinline__ float red_max16(float v) {
#pragma unroll
    for (int o = 8; o; o >>= 1) v = fmaxf(v, __shfl_xor_sync(0xffffffffu, v, o));
    return v;
}
__device__ __forceinline__ float red_sum16(float v) {
#pragma unroll
    for (int o = 8; o; o >>= 1) v += __shfl_xor_sync(0xffffffffu, v, o);
    return v;
}
__device__ __forceinline__ void red_argmax16(float& v, int& idx) {
#pragma unroll
    for (int o = 8; o; o >>= 1) {
        float ov = __shfl_xor_sync(0xffffffffu, v, o);
        int   oi = __shfl_xor_sync(0xffffffffu, idx, o);
        if (ov > v || (ov == v && oi < idx)) { v = ov; idx = oi; }
    }
}

// ---------------- main fused kernel ---------------------------------------
__global__ void __launch_bounds__(256, 1)
vq_main(const float* __restrict__ z, const float* __restrict__ cb,
        float* __restrict__ out)
{
    extern __shared__ float sm[];
    float* Zs = sm;                       // [64][256]
    float* Cs = Zs + BR * DIM;            // [64][257]
    float* Ss = Cs + KT * CS_PITCH;       // [64][66]  (P tile + reduce buffer)

    const int tid  = threadIdx.x;
    const int wrow = tid >> 4;            // 0..15 : row group (4 rows each)
    const int l16  = tid & 15;            // 0..15 : column lane in group
    const int rowBase = blockIdx.x * BR;

    // Load Z tile (resident for whole kernel)
    {
        const float4* zg = (const float4*)(z + (size_t)rowBase * DIM);
        float4* zs4 = (float4*)Zs;
#pragma unroll
        for (int it = 0; it < (BR * DIM / 4) / 256; it++)
            zs4[tid + it * 256] = zg[tid + it * 256];
    }

    // Per-row online state (replicated across the 16 lanes of a row group)
    float mg[4], lg[4], m0v[4], l0v[4], t0v[4], amv[4];
    int   ami[4];
#pragma unroll
    for (int i = 0; i < 4; i++) {
        mg[i] = -INFINITY; lg[i] = 0.f;
        m0v[i] = -INFINITY; l0v[i] = 0.f; t0v[i] = 0.f;
        amv[i] = -INFINITY; ami[i] = 0;
    }

    float acc[4][16];                     // z_q numerator: rows (wrow*4+i) x dims (l16+16q)
#pragma unroll
    for (int i = 0; i < 4; i++)
#pragma unroll
        for (int q = 0; q < 16; q++) acc[i][q] = 0.f;

    for (int ct = 0; ct < NTILE; ct++) {
        __syncthreads();                  // protect Cs/Ss from previous tile's readers
        // Load codebook tile [64 codes x 256 dims] into padded smem
        {
            const float4* cg = (const float4*)(cb + (size_t)ct * KT * DIM);
#pragma unroll
            for (int it = 0; it < (KT * DIM / 4) / 256; it++) {
                int i = tid + it * 256;
                float4 v = cg[i];
                int code = i >> 6;
                int c4 = (i & 63) << 2;
                float* dst = &Cs[code * CS_PITCH + c4];
                dst[0] = v.x; dst[1] = v.y; dst[2] = v.z; dst[3] = v.w;
            }
        }
        __syncthreads();

        // ---- GEMM1: S[4][4] = Z_tile @ C_tile^T ----
        float s[4][4];
#pragma unroll
        for (int i = 0; i < 4; i++)
#pragma unroll
            for (int j = 0; j < 4; j++) s[i][j] = 0.f;

#pragma unroll 2
        for (int k = 0; k < DIM; k += 4) {
            float zk[4][4];
#pragma unroll
            for (int i = 0; i < 4; i++) {
                float4 t = *(const float4*)&Zs[(wrow * 4 + i) * DIM + k];
                zk[i][0] = t.x; zk[i][1] = t.y; zk[i][2] = t.z; zk[i][3] = t.w;
            }
#pragma unroll
            for (int j = 0; j < 4; j++) {
                const float* cp = &Cs[(l16 + 16 * j) * CS_PITCH + k];
                float c0 = cp[0], c1 = cp[1], c2 = cp[2], c3 = cp[3];
#pragma unroll
                for (int i = 0; i < 4; i++) {
                    s[i][j] = fmaf(zk[i][0], c0, s[i][j]);
                    s[i][j] = fmaf(zk[i][1], c1, s[i][j]);
                    s[i][j] = fmaf(zk[i][2], c2, s[i][j]);
                    s[i][j] = fmaf(zk[i][3], c3, s[i][j]);
                }
            }
        }

        // ---- gumbel + online softmax stats (both noised and clean) ----
        float sc[4];
#pragma unroll
        for (int i = 0; i < 4; i++) {
            const uint32_t gr = (uint32_t)(rowBase + wrow * 4 + i);
            float xj[4], yv[4], pj[4];
            float ymax = -INFINITY;
#pragma unroll
            for (int j = 0; j < 4; j++) {
                float x = s[i][j];
                uint32_t c = (uint32_t)(ct * KT + l16 + 16 * j);
                float g = gumbel_rc(gr, c);
                float y = x + g;          // TAU = 1.0
                xj[j] = x; yv[j] = y;
                ymax = fmaxf(ymax, y);
            }
            ymax = red_max16(ymax);
            float nmg = fmaxf(mg[i], ymax);
            float psum = 0.f;
#pragma unroll
            for (int j = 0; j < 4; j++) { pj[j] = __expf(yv[j] - nmg); psum += pj[j]; }
            psum = red_sum16(psum);
            float scale = __expf(mg[i] - nmg);
            lg[i] = lg[i] * scale + psum;
            sc[i] = scale;
            mg[i] = nmg;
#pragma unroll
            for (int j = 0; j < 4; j++)
                Ss[(wrow * 4 + i) * SS_PITCH + l16 + 16 * j] = pj[j];

            // clean-logit stats: max/argmax, l0 = sum e^(x-m0), t0 = sum e^(x-m0)*x
            float xm = xj[0]; int xi = ct * KT + l16;
#pragma unroll
            for (int j = 1; j < 4; j++)
                if (xj[j] > xm) { xm = xj[j]; xi = ct * KT + l16 + 16 * j; }
            red_argmax16(xm, xi);
            float nm0 = fmaxf(m0v[i], xm);
            float es = 0.f, exs = 0.f;
#pragma unroll
            for (int j = 0; j < 4; j++) {
                float e = __expf(xj[j] - nm0);
                es += e;
                exs = fmaf(e, xj[j], exs);
            }
            es  = red_sum16(es);
            exs = red_sum16(exs);
            float s0 = __expf(m0v[i] - nm0);
            l0v[i] = l0v[i] * s0 + es;
            t0v[i] = fmaf(t0v[i], s0, exs);
            m0v[i] = nm0;
            if (xm > amv[i] || (xm == amv[i] && xi < ami[i])) { amv[i] = xm; ami[i] = xi; }
        }

        // ---- PV: acc = acc*scale + P @ C_tile ----
#pragma unroll
        for (int i = 0; i < 4; i++)
#pragma unroll
            for (int q = 0; q < 16; q++) acc[i][q] *= sc[i];

        __syncthreads();                  // Ss fully written
#pragma unroll 2
        for (int j = 0; j < KT; j++) {
            float p0 = Ss[(wrow * 4 + 0) * SS_PITCH + j];
            float p1 = Ss[(wrow * 4 + 1) * SS_PITCH + j];
            float p2 = Ss[(wrow * 4 + 2) * SS_PITCH + j];
            float p3 = Ss[(wrow * 4 + 3) * SS_PITCH + j];
            const float* crow = &Cs[j * CS_PITCH + l16];
#pragma unroll
            for (int q = 0; q < 16; q++) {
                float cv = crow[16 * q];
                acc[0][q] = fmaf(p0, cv, acc[0][q]);
                acc[1][q] = fmaf(p1, cv, acc[1][q]);
                acc[2][q] = fmaf(p2, cv, acc[2][q]);
                acc[3][q] = fmaf(p3, cv, acc[3][q]);
            }
        }
    }

    // ---- epilogue: z_q out, commit partial, KL row terms, codes ----
    float csum = 0.f;
#pragma unroll
    for (int i = 0; i < 4; i++) {
        int gr = rowBase + wrow * 4 + i;
        float inv = 1.0f / lg[i];
#pragma unroll
        for (int q = 0; q < 16; q++) {
            int d = l16 + 16 * q;
            float zq = acc[i][q] * inv;
            out[(size_t)gr * DIM + d] = zq;          // z_q_st == z_q numerically
            float diff = zq - Zs[(wrow * 4 + i) * DIM + d];
            csum = fmaf(diff, diff, csum);
        }
    }
    float ksum = 0.f;
    if (l16 == 0) {
#pragma unroll
        for (int i = 0; i < 4; i++) {
            int gr = rowBase + wrow * 4 + i;
            // KL_row = sum qy*log(qy*K + 1e-10) ~= t0/l0 - m0 - log(l0) + log(K)
            ksum += t0v[i] / l0v[i] - m0v[i] - logf(l0v[i]) + LOGK;
            out[NZ + 1 + gr] = (float)ami[i];        // codes
        }
    }

    // deterministic CTA reductions (fixed tree)
    __syncthreads();
    Ss[tid] = csum;
    __syncthreads();
    for (int st = 128; st > 0; st >>= 1) {
        if (tid < st) Ss[tid] += Ss[tid + st];
        __syncthreads();
    }
    if (tid == 0) g_commitPart[blockIdx.x] = Ss[0];
    __syncthreads();
    Ss[tid] = ksum;
    __syncthreads();
    for (int st = 128; st > 0; st >>= 1) {
        if (tid < st) Ss[tid] += Ss[tid + st];
        __syncthreads();
    }
    if (tid == 0) g_klPart[blockIdx.x] = Ss[0];
}

// ---------------- final deterministic loss reduction ----------------------
__global__ void vq_finish(float* __restrict__ out)
{
    __shared__ float sb[NBLK];
    int t = threadIdx.x;
    sb[t] = g_commitPart[t];
    __syncthreads();
    for (int s = NBLK / 2; s > 0; s >>= 1) {
        if (t < s) sb[t] += sb[t + s];
        __syncthreads();
    }
    float commit = sb[0];
    __syncthreads();
    sb[t] = g_klPart[t];
    __syncthreads();
    for (int s = NBLK / 2; s > 0; s >>= 1) {
        if (t < s) sb[t] += sb[t + s];
        __syncthreads();
    }
    float kl = sb[0];
    if (t == 0)
        out[NZ] = 0.25f * (commit * (1.0f / (float)NZ))
                + 0.01f * (kl * (1.0f / (float)NROWS));
}

extern "C" void kernel_launch(void* const* d_in, const int* in_sizes, int n_in,
                              void* d_out, int out_size)
{
    const float* z  = (const float*)d_in[0];   // (8,64,32,256) fp32
    const float* cb = (const float*)d_in[1];   // (8192,256) fp32
    float* out = (float*)d_out;

    const int smemBytes = (BR * DIM + KT * CS_PITCH + BR * SS_PITCH) * 4; // 148224
    cudaFuncSetAttribute(vq_main, cudaFuncAttributeMaxDynamicSharedMemorySize, smemBytes);

    vq_main<<<NBLK, 256, smemBytes>>>(z, cb, out);
    vq_finish<<<1, NBLK>>>(out);
}

// round 4
// speedup vs baseline: 1.0561x; 1.0561x over previous
#include <cuda_runtime.h>
#include <stdint.h>
#include <math.h>

// VectorQuantizerGumbel — fused single-pass (flash-style) fp32 kernel.
// Outputs (flattened, float32): z_q_st [16384*256], total_loss [1], codes [16384].

#define NROWS   16384
#define NCODES  8192
#define DIM     256
#define BR      64          // rows per CTA
#define KT      64          // codes per tile
#define NZ      (NROWS*DIM) // 4194304
#define CS_PITCH 257        // odd pitch -> conflict-free strided column reads
#define SS_PITCH 66
#define NBLK    (NROWS/BR)  // 256
#define NTILE   (NCODES/KT) // 128
#define LOGK    9.0109133f  // ln(8192)

__device__ float g_commitPart[NBLK];
__device__ float g_klPart[NBLK];

// ---------------- threefry2x32, key = (0, 42)  (jax.random.key(42)) -------
__device__ __forceinline__ uint32_t tf_rotl(uint32_t x, int d) {
    return __funnelshift_l(x, x, d);
}

__device__ __forceinline__ uint2 threefry_0_42(uint32_t x0, uint32_t x1) {
    const uint32_t ks0 = 0u, ks1 = 42u, ks2 = 0u ^ 42u ^ 0x1BD11BDAu;
    x0 += ks0; x1 += ks1;
#define TFR(R) { x0 += x1; x1 = tf_rotl(x1,(R)); x1 ^= x0; }
    TFR(13) TFR(15) TFR(26) TFR(6)
    x0 += ks1; x1 += ks2 + 1u;
    TFR(17) TFR(29) TFR(16) TFR(24)
    x0 += ks2; x1 += ks0 + 2u;
    TFR(13) TFR(15) TFR(26) TFR(6)
    x0 += ks0; x1 += ks1 + 3u;
    TFR(17) TFR(29) TFR(16) TFR(24)
    x0 += ks1; x1 += ks2 + 4u;
    TFR(13) TFR(15) TFR(26) TFR(6)
    x0 += ks2; x1 += ks0 + 5u;
#undef TFR
    return make_uint2(x0, x1);
}

__device__ __forceinline__ float gumbel_from_bits(uint32_t b) {
    // JAX uniform: f = bitcast(bits>>9 | 1.0f_bits) - 1 ; u = max(tiny, f)
    float f = __uint_as_float((b >> 9) | 0x3f800000u) - 1.0f;
    float u = fmaxf(f, 1.17549435e-38f);
    float w = -logf(u);          // accurate log: u near 1 -> tiny w, must be precise
    return -__logf(w);           // outer log: fast version is fine
}

// jax_threefry_partitionable=True (default in modern JAX):
// counter = uint64 flat index -> (x0, x1) = (hi32, lo32); 32-bit draw = out.x ^ out.y
__device__ __forceinline__ float gumbel_rc(uint32_t r, uint32_t c) {
    uint32_t m = r * (uint32_t)NCODES + c;   // flat index into (16384, 8192), < 2^27
    uint2 o = threefry_0_42(0u, m);
    return gumbel_from_bits(o.x ^ o.y);
}

// ---------------- 16-lane butterfly reductions ----------------------------
__device__ __forceinline__ float red_max16(float v) {
#pragma unroll
    for (int o = 8; o; o >>= 1) v = fmaxf(v, __shfl_xor_sync(0xffffffffu, v, o));
    return v;
}
__device__ __forceinline__ float red_sum16(float v) {
#pragma unroll
    for (int o = 8; o; o >>= 1) v += __shfl_xor_sync(0xffffffffu, v, o);
    return v;
}
__device__ __forceinline__ void red_argmax16(float& v, int& idx) {
#pragma unroll
    for (int o = 8; o; o >>= 1) {
        float ov = __shfl_xor_sync(0xffffffffu, v, o);
        int   oi = __shfl_xor_sync(0xffffffffu, idx, o);
        if (ov > v || (ov == v && oi < idx)) { v = ov; idx = oi; }
    }
}

// ---------------- main fused kernel ---------------------------------------
__global__ void __launch_bounds__(256, 1)
vq_main(const float* __restrict__ z, const float* __restrict__ cb,
        float* __restrict__ out)
{
    extern __shared__ float sm[];
    float* Zs = sm;                       // [64][256]
    float* Cs = Zs + BR * DIM;            // [64][257]
    float* Ss = Cs + KT * CS_PITCH;       // [64][66]  (P tile + reduce buffer)

    const int tid  = threadIdx.x;
    const int wrow = tid >> 4;            // 0..15 : row group (4 rows each)
    const int l16  = tid & 15;            // 0..15 : column lane in group
    const int rowBase = blockIdx.x * BR;

    // Load Z tile (resident for whole kernel)
    {
        const float4* zg = (const float4*)(z + (size_t)rowBase * DIM);
        float4* zs4 = (float4*)Zs;
#pragma unroll
        for (int it = 0; it < (BR * DIM / 4) / 256; it++)
            zs4[tid + it * 256] = zg[tid + it * 256];
    }

    // Per-row online state (replicated across the 16 lanes of a row group)
    float mg[4], lg[4], m0v[4], l0v[4], t0v[4], amv[4];
    int   ami[4];
#pragma unroll
    for (int i = 0; i < 4; i++) {
        mg[i] = -INFINITY; lg[i] = 0.f;
        m0v[i] = -INFINITY; l0v[i] = 0.f; t0v[i] = 0.f;
        amv[i] = -INFINITY; ami[i] = 0;
    }

    float acc[4][16];                     // z_q numerator: rows (wrow*4+i) x dims (l16+16q)
#pragma unroll
    for (int i = 0; i < 4; i++)
#pragma unroll
        for (int q = 0; q < 16; q++) acc[i][q] = 0.f;

    for (int ct = 0; ct < NTILE; ct++) {
        __syncthreads();                  // protect Cs/Ss from previous tile's readers
        // Load codebook tile [64 codes x 256 dims] into padded smem
        {
            const float4* cg = (const float4*)(cb + (size_t)ct * KT * DIM);
#pragma unroll
            for (int it = 0; it < (KT * DIM / 4) / 256; it++) {
                int i = tid + it * 256;
                float4 v = cg[i];
                int code = i >> 6;
                int c4 = (i & 63) << 2;
                float* dst = &Cs[code * CS_PITCH + c4];
                dst[0] = v.x; dst[1] = v.y; dst[2] = v.z; dst[3] = v.w;
            }
        }
        __syncthreads();

        // ---- GEMM1: S[4][4] = Z_tile @ C_tile^T ----
        float s[4][4];
#pragma unroll
        for (int i = 0; i < 4; i++)
#pragma unroll
            for (int j = 0; j < 4; j++) s[i][j] = 0.f;

#pragma unroll 2
        for (int k = 0; k < DIM; k += 4) {
            float zk[4][4];
#pragma unroll
            for (int i = 0; i < 4; i++) {
                float4 t = *(const float4*)&Zs[(wrow * 4 + i) * DIM + k];
                zk[i][0] = t.x; zk[i][1] = t.y; zk[i][2] = t.z; zk[i][3] = t.w;
            }
#pragma unroll
            for (int j = 0; j < 4; j++) {
                const float* cp = &Cs[(l16 + 16 * j) * CS_PITCH + k];
                float c0 = cp[0], c1 = cp[1], c2 = cp[2], c3 = cp[3];
#pragma unroll
                for (int i = 0; i < 4; i++) {
                    s[i][j] = fmaf(zk[i][0], c0, s[i][j]);
                    s[i][j] = fmaf(zk[i][1], c1, s[i][j]);
                    s[i][j] = fmaf(zk[i][2], c2, s[i][j]);
                    s[i][j] = fmaf(zk[i][3], c3, s[i][j]);
                }
            }
        }

        // ---- gumbel + online softmax stats (both noised and clean) ----
        float sc[4];
#pragma unroll
        for (int i = 0; i < 4; i++) {
            const uint32_t gr = (uint32_t)(rowBase + wrow * 4 + i);
            float xj[4], yv[4], pj[4];
            float ymax = -INFINITY;
#pragma unroll
            for (int j = 0; j < 4; j++) {
                float x = s[i][j];
                uint32_t c = (uint32_t)(ct * KT + l16 + 16 * j);
                float g = gumbel_rc(gr, c);
                float y = x + g;          // TAU = 1.0
                xj[j] = x; yv[j] = y;
                ymax = fmaxf(ymax, y);
            }
            ymax = red_max16(ymax);
            float nmg = fmaxf(mg[i], ymax);
            float psum = 0.f;
#pragma unroll
            for (int j = 0; j < 4; j++) { pj[j] = __expf(yv[j] - nmg); psum += pj[j]; }
            psum = red_sum16(psum);
            float scale = __expf(mg[i] - nmg);
            lg[i] = lg[i] * scale + psum;
            sc[i] = scale;
            mg[i] = nmg;
#pragma unroll
            for (int j = 0; j < 4; j++)
                Ss[(wrow * 4 + i) * SS_PITCH + l16 + 16 * j] = pj[j];

            // clean-logit stats: max/argmax, l0 = sum e^(x-m0), t0 = sum e^(x-m0)*x
            float xm = xj[0]; int xi = ct * KT + l16;
#pragma unroll
            for (int j = 1; j < 4; j++)
                if (xj[j] > xm) { xm = xj[j]; xi = ct * KT + l16 + 16 * j; }
            red_argmax16(xm, xi);
            float nm0 = fmaxf(m0v[i], xm);
            float es = 0.f, exs = 0.f;
#pragma unroll
            for (int j = 0; j < 4; j++) {
                float e = __expf(xj[j] - nm0);
                es += e;
                exs = fmaf(e, xj[j], exs);
            }
            es  = red_sum16(es);
            exs = red_sum16(exs);
            float s0 = __expf(m0v[i] - nm0);
            l0v[i] = l0v[i] * s0 + es;
            t0v[i] = fmaf(t0v[i], s0, exs);
            m0v[i] = nm0;
            if (xm > amv[i] || (xm == amv[i] && xi < ami[i])) { amv[i] = xm; ami[i] = xi; }
        }

        // ---- PV: acc = acc*scale + P @ C_tile ----
#pragma unroll
        for (int i = 0; i < 4; i++)
#pragma unroll
            for (int q = 0; q < 16; q++) acc[i][q] *= sc[i];

        __syncthreads();                  // Ss fully written
#pragma unroll 2
        for (int j = 0; j < KT; j++) {
            float p0 = Ss[(wrow * 4 + 0) * SS_PITCH + j];
            float p1 = Ss[(wrow * 4 + 1) * SS_PITCH + j];
            float p2 = Ss[(wrow * 4 + 2) * SS_PITCH + j];
            float p3 = Ss[(wrow * 4 + 3) * SS_PITCH + j];
            const float* crow = &Cs[j * CS_PITCH + l16];
#pragma unroll
            for (int q = 0; q < 16; q++) {
                float cv = crow[16 * q];
                acc[0][q] = fmaf(p0, cv, acc[0][q]);
                acc[1][q] = fmaf(p1, cv, acc[1][q]);
                acc[2][q] = fmaf(p2, cv, acc[2][q]);
                acc[3][q] = fmaf(p3, cv, acc[3][q]);
            }
        }
    }

    // ---- epilogue: z_q out, commit partial, KL row terms, codes ----
    float csum = 0.f;
#pragma unroll
    for (int i = 0; i < 4; i++) {
        int gr = rowBase + wrow * 4 + i;
        float inv = 1.0f / lg[i];
#pragma unroll
        for (int q = 0; q < 16; q++) {
            int d = l16 + 16 * q;
            float zq = acc[i][q] * inv;
            out[(size_t)gr * DIM + d] = zq;          // z_q_st == z_q numerically
            float diff = zq - Zs[(wrow * 4 + i) * DIM + d];
            csum = fmaf(diff, diff, csum);
        }
    }
    float ksum = 0.f;
    if (l16 == 0) {
#pragma unroll
        for (int i = 0; i < 4; i++) {
            int gr = rowBase + wrow * 4 + i;
            // KL_row = sum qy*log(qy*K + 1e-10) ~= t0/l0 - m0 - log(l0) + log(K)
            ksum += t0v[i] / l0v[i] - m0v[i] - logf(l0v[i]) + LOGK;
            out[NZ + 1 + gr] = (float)ami[i];        // codes
        }
    }

    // deterministic CTA reductions (fixed tree)
    __syncthreads();
    Ss[tid] = csum;
    __syncthreads();
    for (int st = 128; st > 0; st >>= 1) {
        if (tid < st) Ss[tid] += Ss[tid + st];
        __syncthreads();
    }
    if (tid == 0) g_commitPart[blockIdx.x] = Ss[0];
    __syncthreads();
    Ss[tid] = ksum;
    __syncthreads();
    for (int st = 128; st > 0; st >>= 1) {
        if (tid < st) Ss[tid] += Ss[tid + st];
        __syncthreads();
    }
    if (tid == 0) g_klPart[blockIdx.x] = Ss[0];
}

// ---------------- final deterministic loss reduction ----------------------
__global__ void vq_finish(float* __restrict__ out)
{
    __shared__ float sb[NBLK];
    int t = threadIdx.x;
    sb[t] = g_commitPart[t];
    __syncthreads();
    for (int s = NBLK / 2; s > 0; s >>= 1) {
        if (t < s) sb[t] += sb[t + s];
        __syncthreads();
    }
    float commit = sb[0];
    __syncthreads();
    sb[t] = g_klPart[t];
    __syncthreads();
    for (int s = NBLK / 2; s > 0; s >>= 1) {
        if (t < s) sb[t] += sb[t + s];
        __syncthreads();
    }
    float kl = sb[0];
    if (t == 0)
        out[NZ] = 0.25f * (commit * (1.0f / (float)NZ))
                + 0.01f * (kl * (1.0f / (float)NROWS));
}

extern "C" void kernel_launch(void* const* d_in, const int* in_sizes, int n_in,
                              void* d_out, int out_size)
{
    const float* z  = (const float*)d_in[0];   // (8,64,32,256) fp32
    const float* cb = (const float*)d_in[1];   // (8192,256) fp32
    float* out = (float*)d_out;

    const int smemBytes = (BR * DIM + KT * CS_PITCH + BR * SS_PITCH) * 4; // 148224
    cudaFuncSetAttribute(vq_main, cudaFuncAttributeMaxDynamicSharedMemorySize, smemBytes);

    vq_main<<<NBLK, 256, smemBytes>>>(z, cb, out);
    vq_finish<<<1, NBLK>>>(out);
}

// round 5
// speedup vs baseline: 1.0578x; 1.0016x over previous
#include <cuda_runtime.h>
#include <stdint.h>
#include <math.h>

// VectorQuantizerGumbel — fused single-pass (flash-style) fp32 kernel.
// Outputs (flattened, float32): z_q_st [16384*256], total_loss [1], codes [16384].

#define NROWS   16384
#define NCODES  8192
#define DIM     256
#define BR      64          // rows per CTA
#define KT      64          // codes per tile
#define NZ      (NROWS*DIM) // 4194304
#define CS_PITCH 257        // odd pitch -> conflict-free strided column reads
#define SS_PITCH 66
#define NBLK    (NROWS/BR)  // 256
#define NTILE   (NCODES/KT) // 128
#define LOGK    9.0109133f  // ln(8192)

__device__ float g_commitPart[NBLK];
__device__ float g_klPart[NBLK];

// ---------------- threefry2x32, key = (0, 42)  (jax.random.key(42)) -------
__device__ __forceinline__ uint32_t tf_rotl(uint32_t x, int d) {
    return __funnelshift_l(x, x, d);
}

__device__ __forceinline__ uint2 threefry_0_42(uint32_t x0, uint32_t x1) {
    const uint32_t ks0 = 0u, ks1 = 42u, ks2 = 0u ^ 42u ^ 0x1BD11BDAu;
    x0 += ks0; x1 += ks1;
#define TFR(R) { x0 += x1; x1 = tf_rotl(x1,(R)); x1 ^= x0; }
    TFR(13) TFR(15) TFR(26) TFR(6)
    x0 += ks1; x1 += ks2 + 1u;
    TFR(17) TFR(29) TFR(16) TFR(24)
    x0 += ks2; x1 += ks0 + 2u;
    TFR(13) TFR(15) TFR(26) TFR(6)
    x0 += ks0; x1 += ks1 + 3u;
    TFR(17) TFR(29) TFR(16) TFR(24)
    x0 += ks1; x1 += ks2 + 4u;
    TFR(13) TFR(15) TFR(26) TFR(6)
    x0 += ks2; x1 += ks0 + 5u;
#undef TFR
    return make_uint2(x0, x1);
}

__device__ __forceinline__ float gumbel_from_bits(uint32_t b) {
    // JAX uniform: f = bitcast(bits>>9 | 1.0f_bits) - 1 ; u = max(tiny, f)
    float f = __uint_as_float((b >> 9) | 0x3f800000u) - 1.0f;
    float u = fmaxf(f, 1.17549435e-38f);
    float w = -logf(u);          // accurate log: u near 1 -> tiny w, must be precise
    return -__logf(w);           // outer log: fast version is fine
}

// jax_threefry_partitionable=True (default in modern JAX):
// counter = uint64 flat index -> (x0, x1) = (hi32, lo32); 32-bit draw = out.x ^ out.y
__device__ __forceinline__ float gumbel_rc(uint32_t r, uint32_t c) {
    uint32_t m = r * (uint32_t)NCODES + c;   // flat index into (16384, 8192), < 2^27
    uint2 o = threefry_0_42(0u, m);
    return gumbel_from_bits(o.x ^ o.y);
}

// ---------------- 16-lane butterfly reductions ----------------------------
__device__ __forceinline__ float red_max16(float v) {
#pragma unroll
    for (int o = 8; o; o >>= 1) v = fmaxf(v, __shfl_xor_sync(0xffffffffu, v, o));
    return v;
}
__device__ __forceinline__ float red_sum16(float v) {
#pragma unroll
    for (int o = 8; o; o >>= 1) v += __shfl_xor_sync(0xffffffffu, v, o);
    return v;
}
__device__ __forceinline__ void red_argmax16(float& v, int& idx) {
#pragma unroll
    for (int o = 8; o; o >>= 1) {
        float ov = __shfl_xor_sync(0xffffffffu, v, o);
        int   oi = __shfl_xor_sync(0xffffffffu, idx, o);
        if (ov > v || (ov == v && oi < idx)) { v = ov; idx = oi; }
    }
}

// ---------------- main fused kernel ---------------------------------------
__global__ void __launch_bounds__(256, 1)
vq_main(const float* __restrict__ z, const float* __restrict__ cb,
        float* __restrict__ out)
{
    extern __shared__ float sm[];
    float* Zs = sm;                       // [64][256]
    float* Cs = Zs + BR * DIM;            // [64][257]
    float* Ss = Cs + KT * CS_PITCH;       // [64][66]  (P tile + reduce buffer)

    const int tid  = threadIdx.x;
    const int wrow = tid >> 4;            // 0..15 : row group (4 rows each)
    const int l16  = tid & 15;            // 0..15 : column lane in group
    const int rowBase = blockIdx.x * BR;

    // Load Z tile (resident for whole kernel)
    {
        const float4* zg = (const float4*)(z + (size_t)rowBase * DIM);
        float4* zs4 = (float4*)Zs;
#pragma unroll
        for (int it = 0; it < (BR * DIM / 4) / 256; it++)
            zs4[tid + it * 256] = zg[tid + it * 256];
    }

    // Per-row online state (replicated across the 16 lanes of a row group)
    float mg[4], lg[4], m0v[4], l0v[4], t0v[4], amv[4];
    int   ami[4];
#pragma unroll
    for (int i = 0; i < 4; i++) {
        mg[i] = -INFINITY; lg[i] = 0.f;
        m0v[i] = -INFINITY; l0v[i] = 0.f; t0v[i] = 0.f;
        amv[i] = -INFINITY; ami[i] = 0;
    }

    float acc[4][16];                     // z_q numerator: rows (wrow*4+i) x dims (l16+16q)
#pragma unroll
    for (int i = 0; i < 4; i++)
#pragma unroll
        for (int q = 0; q < 16; q++) acc[i][q] = 0.f;

    for (int ct = 0; ct < NTILE; ct++) {
        __syncthreads();                  // protect Cs/Ss from previous tile's readers
        // Load codebook tile [64 codes x 256 dims] into padded smem
        {
            const float4* cg = (const float4*)(cb + (size_t)ct * KT * DIM);
#pragma unroll
            for (int it = 0; it < (KT * DIM / 4) / 256; it++) {
                int i = tid + it * 256;
                float4 v = cg[i];
                int code = i >> 6;
                int c4 = (i & 63) << 2;
                float* dst = &Cs[code * CS_PITCH + c4];
                dst[0] = v.x; dst[1] = v.y; dst[2] = v.z; dst[3] = v.w;
            }
        }
        __syncthreads();

        // ---- GEMM1: S[4][4] = Z_tile @ C_tile^T ----
        float s[4][4];
#pragma unroll
        for (int i = 0; i < 4; i++)
#pragma unroll
            for (int j = 0; j < 4; j++) s[i][j] = 0.f;

#pragma unroll 2
        for (int k = 0; k < DIM; k += 4) {
            float zk[4][4];
#pragma unroll
            for (int i = 0; i < 4; i++) {
                float4 t = *(const float4*)&Zs[(wrow * 4 + i) * DIM + k];
                zk[i][0] = t.x; zk[i][1] = t.y; zk[i][2] = t.z; zk[i][3] = t.w;
            }
#pragma unroll
            for (int j = 0; j < 4; j++) {
                const float* cp = &Cs[(l16 + 16 * j) * CS_PITCH + k];
                float c0 = cp[0], c1 = cp[1], c2 = cp[2], c3 = cp[3];
#pragma unroll
                for (int i = 0; i < 4; i++) {
                    s[i][j] = fmaf(zk[i][0], c0, s[i][j]);
                    s[i][j] = fmaf(zk[i][1], c1, s[i][j]);
                    s[i][j] = fmaf(zk[i][2], c2, s[i][j]);
                    s[i][j] = fmaf(zk[i][3], c3, s[i][j]);
                }
            }
        }

        // ---- gumbel + online softmax stats (both noised and clean) ----
        float sc[4];
#pragma unroll
        for (int i = 0; i < 4; i++) {
            const uint32_t gr = (uint32_t)(rowBase + wrow * 4 + i);
            float xj[4], yv[4], pj[4];
            float ymax = -INFINITY;
#pragma unroll
            for (int j = 0; j < 4; j++) {
                float x = s[i][j];
                uint32_t c = (uint32_t)(ct * KT + l16 + 16 * j);
                float g = gumbel_rc(gr, c);
                float y = x + g;          // TAU = 1.0
                xj[j] = x; yv[j] = y;
                ymax = fmaxf(ymax, y);
            }
            ymax = red_max16(ymax);
            float nmg = fmaxf(mg[i], ymax);
            float psum = 0.f;
#pragma unroll
            for (int j = 0; j < 4; j++) { pj[j] = __expf(yv[j] - nmg); psum += pj[j]; }
            psum = red_sum16(psum);
            float scale = __expf(mg[i] - nmg);
            lg[i] = lg[i] * scale + psum;
            sc[i] = scale;
            mg[i] = nmg;
#pragma unroll
            for (int j = 0; j < 4; j++)
                Ss[(wrow * 4 + i) * SS_PITCH + l16 + 16 * j] = pj[j];

            // clean-logit stats: max/argmax, l0 = sum e^(x-m0), t0 = sum e^(x-m0)*x
            float xm = xj[0]; int xi = ct * KT + l16;
#pragma unroll
            for (int j = 1; j < 4; j++)
                if (xj[j] > xm) { xm = xj[j]; xi = ct * KT + l16 + 16 * j; }
            red_argmax16(xm, xi);
            float nm0 = fmaxf(m0v[i], xm);
            float es = 0.f, exs = 0.f;
#pragma unroll
            for (int j = 0; j < 4; j++) {
                float e = __expf(xj[j] - nm0);
                es += e;
                exs = fmaf(e, xj[j], exs);
            }
            es  = red_sum16(es);
            exs = red_sum16(exs);
            float s0 = __expf(m0v[i] - nm0);
            l0v[i] = l0v[i] * s0 + es;
            t0v[i] = fmaf(t0v[i], s0, exs);
            m0v[i] = nm0;
            if (xm > amv[i] || (xm == amv[i] && xi < ami[i])) { amv[i] = xm; ami[i] = xi; }
        }

        // ---- PV: acc = acc*scale + P @ C_tile ----
#pragma unroll
        for (int i = 0; i < 4; i++)
#pragma unroll
            for (int q = 0; q < 16; q++) acc[i][q] *= sc[i];

        __syncthreads();                  // Ss fully written
#pragma unroll 2
        for (int j = 0; j < KT; j++) {
            float p0 = Ss[(wrow * 4 + 0) * SS_PITCH + j];
            float p1 = Ss[(wrow * 4 + 1) * SS_PITCH + j];
            float p2 = Ss[(wrow * 4 + 2) * SS_PITCH + j];
            float p3 = Ss[(wrow * 4 + 3) * SS_PITCH + j];
            const float* crow = &Cs[j * CS_PITCH + l16];
#pragma unroll
            for (int q = 0; q < 16; q++) {
                float cv = crow[16 * q];
                acc[0][q] = fmaf(p0, cv, acc[0][q]);
                acc[1][q] = fmaf(p1, cv, acc[1][q]);
                acc[2][q] = fmaf(p2, cv, acc[2][q]);
                acc[3][q] = fmaf(p3, cv, acc[3][q]);
            }
        }
    }

    // ---- epilogue: z_q out, commit partial, KL row terms, codes ----
    float csum = 0.f;
#pragma unroll
    for (int i = 0; i < 4; i++) {
        int gr = rowBase + wrow * 4 + i;
        float inv = 1.0f / lg[i];
#pragma unroll
        for (int q = 0; q < 16; q++) {
            int d = l16 + 16 * q;
            float zq = acc[i][q] * inv;
            out[(size_t)gr * DIM + d] = zq;          // z_q_st == z_q numerically
            float diff = zq - Zs[(wrow * 4 + i) * DIM + d];
            csum = fmaf(diff, diff, csum);
        }
    }
    float ksum = 0.f;
    if (l16 == 0) {
#pragma unroll
        for (int i = 0; i < 4; i++) {
            int gr = rowBase + wrow * 4 + i;
            // KL_row = sum qy*log(qy*K + 1e-10) ~= t0/l0 - m0 - log(l0) + log(K)
            ksum += t0v[i] / l0v[i] - m0v[i] - logf(l0v[i]) + LOGK;
            out[NZ + 1 + gr] = (float)ami[i];        // codes
        }
    }

    // deterministic CTA reductions (fixed tree)
    __syncthreads();
    Ss[tid] = csum;
    __syncthreads();
    for (int st = 128; st > 0; st >>= 1) {
        if (tid < st) Ss[tid] += Ss[tid + st];
        __syncthreads();
    }
    if (tid == 0) g_commitPart[blockIdx.x] = Ss[0];
    __syncthreads();
    Ss[tid] = ksum;
    __syncthreads();
    for (int st = 128; st > 0; st >>= 1) {
        if (tid < st) Ss[tid] += Ss[tid + st];
        __syncthreads();
    }
    if (tid == 0) g_klPart[blockIdx.x] = Ss[0];
}

// ---------------- final deterministic loss reduction ----------------------
__global__ void vq_finish(float* __restrict__ out)
{
    __shared__ float sb[NBLK];
    int t = threadIdx.x;
    sb[t] = g_commitPart[t];
    __syncthreads();
    for (int s = NBLK / 2; s > 0; s >>= 1) {
        if (t < s) sb[t] += sb[t + s];
        __syncthreads();
    }
    float commit = sb[0];
    __syncthreads();
    sb[t] = g_klPart[t];
    __syncthreads();
    for (int s = NBLK / 2; s > 0; s >>= 1) {
        if (t < s) sb[t] += sb[t + s];
        __syncthreads();
    }
    float kl = sb[0];
    if (t == 0)
        out[NZ] = 0.25f * (commit * (1.0f / (float)NZ))
                + 0.01f * (kl * (1.0f / (float)NROWS));
}

extern "C" void kernel_launch(void* const* d_in, const int* in_sizes, int n_in,
                              void* d_out, int out_size)
{
    const float* z  = (const float*)d_in[0];   // (8,64,32,256) fp32
    const float* cb = (const float*)d_in[1];   // (8192,256) fp32
    float* out = (float*)d_out;

    const int smemBytes = (BR * DIM + KT * CS_PITCH + BR * SS_PITCH) * 4; // 148224
    cudaFuncSetAttribute(vq_main, cudaFuncAttributeMaxDynamicSharedMemorySize, smemBytes);

    vq_main<<<NBLK, 256, smemBytes>>>(z, cb, out);
    vq_finish<<<1, NBLK>>>(out);
}

// round 6
// speedup vs baseline: 1.0589x; 1.0010x over previous
#include <cuda_runtime.h>
#include <stdint.h>
#include <math.h>

// VectorQuantizerGumbel — fused single-pass (flash-style) fp32 kernel.
// Outputs (flattened, float32): z_q_st [16384*256], total_loss [1], codes [16384].

#define NROWS   16384
#define NCODES  8192
#define DIM     256
#define BR      64          // rows per CTA
#define KT      64          // codes per tile
#define NZ      (NROWS*DIM) // 4194304
#define CS_PITCH 257        // odd pitch -> conflict-free strided column reads
#define SS_PITCH 66
#define NBLK    (NROWS/BR)  // 256
#define NTILE   (NCODES/KT) // 128
#define LOGK    9.0109133f  // ln(8192)

__device__ float g_commitPart[NBLK];
__device__ float g_klPart[NBLK];

// ---------------- threefry2x32, key = (0, 42)  (jax.random.key(42)) -------
__device__ __forceinline__ uint32_t tf_rotl(uint32_t x, int d) {
    return __funnelshift_l(x, x, d);
}

__device__ __forceinline__ uint2 threefry_0_42(uint32_t x0, uint32_t x1) {
    const uint32_t ks0 = 0u, ks1 = 42u, ks2 = 0u ^ 42u ^ 0x1BD11BDAu;
    x0 += ks0; x1 += ks1;
#define TFR(R) { x0 += x1; x1 = tf_rotl(x1,(R)); x1 ^= x0; }
    TFR(13) TFR(15) TFR(26) TFR(6)
    x0 += ks1; x1 += ks2 + 1u;
    TFR(17) TFR(29) TFR(16) TFR(24)
    x0 += ks2; x1 += ks0 + 2u;
    TFR(13) TFR(15) TFR(26) TFR(6)
    x0 += ks0; x1 += ks1 + 3u;
    TFR(17) TFR(29) TFR(16) TFR(24)
    x0 += ks1; x1 += ks2 + 4u;
    TFR(13) TFR(15) TFR(26) TFR(6)
    x0 += ks2; x1 += ks0 + 5u;
#undef TFR
    return make_uint2(x0, x1);
}

__device__ __forceinline__ float gumbel_from_bits(uint32_t b) {
    // JAX uniform: f = bitcast(bits>>9 | 1.0f_bits) - 1 ; u = max(tiny, f)
    float f = __uint_as_float((b >> 9) | 0x3f800000u) - 1.0f;
    float u = fmaxf(f, 1.17549435e-38f);
    float w = -logf(u);          // accurate log: u near 1 -> tiny w, must be precise
    return -__logf(w);           // outer log: fast version is fine
}

// jax_threefry_partitionable=True (default in modern JAX):
// counter = uint64 flat index -> (x0, x1) = (hi32, lo32); 32-bit draw = out.x ^ out.y
__device__ __forceinline__ float gumbel_rc(uint32_t r, uint32_t c) {
    uint32_t m = r * (uint32_t)NCODES + c;   // flat index into (16384, 8192), < 2^27
    uint2 o = threefry_0_42(0u, m);
    return gumbel_from_bits(o.x ^ o.y);
}

// ---------------- 16-lane butterfly reductions ----------------------------
__device__ __forceinline__ float red_max16(float v) {
#pragma unroll
    for (int o = 8; o; o >>= 1) v = fmaxf(v, __shfl_xor_sync(0xffffffffu, v, o));
    return v;
}
__device__ __forceinline__ float red_sum16(float v) {
#pragma unroll
    for (int o = 8; o; o >>= 1) v += __shfl_xor_sync(0xffffffffu, v, o);
    return v;
}
__device__ __forceinline__ void red_argmax16(float& v, int& idx) {
#pragma unroll
    for (int o = 8; o; o >>= 1) {
        float ov = __shfl_xor_sync(0xffffffffu, v, o);
        int   oi = __shfl_xor_sync(0xffffffffu, idx, o);
        if (ov > v || (ov == v && oi < idx)) { v = ov; idx = oi; }
    }
}

// ---------------- main fused kernel ---------------------------------------
__global__ void __launch_bounds__(256, 1)
vq_main(const float* __restrict__ z, const float* __restrict__ cb,
        float* __restrict__ out)
{
    extern __shared__ float sm[];
    float* Zs = sm;                       // [64][256]
    float* Cs = Zs + BR * DIM;            // [64][257]
    float* Ss = Cs + KT * CS_PITCH;       // [64][66]  (P tile + reduce buffer)

    const int tid  = threadIdx.x;
    const int wrow = tid >> 4;            // 0..15 : row group (4 rows each)
    const int l16  = tid & 15;            // 0..15 : column lane in group
    const int rowBase = blockIdx.x * BR;

    // Load Z tile (resident for whole kernel)
    {
        const float4* zg = (const float4*)(z + (size_t)rowBase * DIM);
        float4* zs4 = (float4*)Zs;
#pragma unroll
        for (int it = 0; it < (BR * DIM / 4) / 256; it++)
            zs4[tid + it * 256] = zg[tid + it * 256];
    }

    // Per-row online state (replicated across the 16 lanes of a row group)
    float mg[4], lg[4], m0v[4], l0v[4], t0v[4], amv[4];
    int   ami[4];
#pragma unroll
    for (int i = 0; i < 4; i++) {
        mg[i] = -INFINITY; lg[i] = 0.f;
        m0v[i] = -INFINITY; l0v[i] = 0.f; t0v[i] = 0.f;
        amv[i] = -INFINITY; ami[i] = 0;
    }

    float acc[4][16];                     // z_q numerator: rows (wrow*4+i) x dims (l16+16q)
#pragma unroll
    for (int i = 0; i < 4; i++)
#pragma unroll
        for (int q = 0; q < 16; q++) acc[i][q] = 0.f;

    for (int ct = 0; ct < NTILE; ct++) {
        __syncthreads();                  // protect Cs/Ss from previous tile's readers
        // Load codebook tile [64 codes x 256 dims] into padded smem
        {
            const float4* cg = (const float4*)(cb + (size_t)ct * KT * DIM);
#pragma unroll
            for (int it = 0; it < (KT * DIM / 4) / 256; it++) {
                int i = tid + it * 256;
                float4 v = cg[i];
                int code = i >> 6;
                int c4 = (i & 63) << 2;
                float* dst = &Cs[code * CS_PITCH + c4];
                dst[0] = v.x; dst[1] = v.y; dst[2] = v.z; dst[3] = v.w;
            }
        }
        __syncthreads();

        // ---- GEMM1: S[4][4] = Z_tile @ C_tile^T ----
        float s[4][4];
#pragma unroll
        for (int i = 0; i < 4; i++)
#pragma unroll
            for (int j = 0; j < 4; j++) s[i][j] = 0.f;

#pragma unroll 2
        for (int k = 0; k < DIM; k += 4) {
            float zk[4][4];
#pragma unroll
            for (int i = 0; i < 4; i++) {
                float4 t = *(const float4*)&Zs[(wrow * 4 + i) * DIM + k];
                zk[i][0] = t.x; zk[i][1] = t.y; zk[i][2] = t.z; zk[i][3] = t.w;
            }
#pragma unroll
            for (int j = 0; j < 4; j++) {
                const float* cp = &Cs[(l16 + 16 * j) * CS_PITCH + k];
                float c0 = cp[0], c1 = cp[1], c2 = cp[2], c3 = cp[3];
#pragma unroll
                for (int i = 0; i < 4; i++) {
                    s[i][j] = fmaf(zk[i][0], c0, s[i][j]);
                    s[i][j] = fmaf(zk[i][1], c1, s[i][j]);
                    s[i][j] = fmaf(zk[i][2], c2, s[i][j]);
                    s[i][j] = fmaf(zk[i][3], c3, s[i][j]);
                }
            }
        }

        // ---- gumbel + online softmax stats (both noised and clean) ----
        float sc[4];
#pragma unroll
        for (int i = 0; i < 4; i++) {
            const uint32_t gr = (uint32_t)(rowBase + wrow * 4 + i);
            float xj[4], yv[4], pj[4];
            float ymax = -INFINITY;
#pragma unroll
            for (int j = 0; j < 4; j++) {
                float x = s[i][j];
                uint32_t c = (uint32_t)(ct * KT + l16 + 16 * j);
                float g = gumbel_rc(gr, c);
                float y = x + g;          // TAU = 1.0
                xj[j] = x; yv[j] = y;
                ymax = fmaxf(ymax, y);
            }
            ymax = red_max16(ymax);
            float nmg = fmaxf(mg[i], ymax);
            float psum = 0.f;
#pragma unroll
            for (int j = 0; j < 4; j++) { pj[j] = __expf(yv[j] - nmg); psum += pj[j]; }
            psum = red_sum16(psum);
            float scale = __expf(mg[i] - nmg);
            lg[i] = lg[i] * scale + psum;
            sc[i] = scale;
            mg[i] = nmg;
#pragma unroll
            for (int j = 0; j < 4; j++)
                Ss[(wrow * 4 + i) * SS_PITCH + l16 + 16 * j] = pj[j];

            // clean-logit stats: max/argmax, l0 = sum e^(x-m0), t0 = sum e^(x-m0)*x
            float xm = xj[0]; int xi = ct * KT + l16;
#pragma unroll
            for (int j = 1; j < 4; j++)
                if (xj[j] > xm) { xm = xj[j]; xi = ct * KT + l16 + 16 * j; }
            red_argmax16(xm, xi);
            float nm0 = fmaxf(m0v[i], xm);
            float es = 0.f, exs = 0.f;
#pragma unroll
            for (int j = 0; j < 4; j++) {
                float e = __expf(xj[j] - nm0);
                es += e;
                exs = fmaf(e, xj[j], exs);
            }
            es  = red_sum16(es);
            exs = red_sum16(exs);
            float s0 = __expf(m0v[i] - nm0);
            l0v[i] = l0v[i] * s0 + es;
            t0v[i] = fmaf(t0v[i], s0, exs);
            m0v[i] = nm0;
            if (xm > amv[i] || (xm == amv[i] && xi < ami[i])) { amv[i] = xm; ami[i] = xi; }
        }

        // ---- PV: acc = acc*scale + P @ C_tile ----
#pragma unroll
        for (int i = 0; i < 4; i++)
#pragma unroll
            for (int q = 0; q < 16; q++) acc[i][q] *= sc[i];

        __syncthreads();                  // Ss fully written
#pragma unroll 2
        for (int j = 0; j < KT; j++) {
            float p0 = Ss[(wrow * 4 + 0) * SS_PITCH + j];
            float p1 = Ss[(wrow * 4 + 1) * SS_PITCH + j];
            float p2 = Ss[(wrow * 4 + 2) * SS_PITCH + j];
            float p3 = Ss[(wrow * 4 + 3) * SS_PITCH + j];
            const float* crow = &Cs[j * CS_PITCH + l16];
#pragma unroll
            for (int q = 0; q < 16; q++) {
                float cv = crow[16 * q];
                acc[0][q] = fmaf(p0, cv, acc[0][q]);
                acc[1][q] = fmaf(p1, cv, acc[1][q]);
                acc[2][q] = fmaf(p2, cv, acc[2][q]);
                acc[3][q] = fmaf(p3, cv, acc[3][q]);
            }
        }
    }

    // ---- epilogue: z_q out, commit partial, KL row terms, codes ----
    float csum = 0.f;
#pragma unroll
    for (int i = 0; i < 4; i++) {
        int gr = rowBase + wrow * 4 + i;
        float inv = 1.0f / lg[i];
#pragma unroll
        for (int q = 0; q < 16; q++) {
            int d = l16 + 16 * q;
            float zq = acc[i][q] * inv;
            out[(size_t)gr * DIM + d] = zq;          // z_q_st == z_q numerically
            float diff = zq - Zs[(wrow * 4 + i) * DIM + d];
            csum = fmaf(diff, diff, csum);
        }
    }
    float ksum = 0.f;
    if (l16 == 0) {
#pragma unroll
        for (int i = 0; i < 4; i++) {
            int gr = rowBase + wrow * 4 + i;
            // KL_row = sum qy*log(qy*K + 1e-10) ~= t0/l0 - m0 - log(l0) + log(K)
            ksum += t0v[i] / l0v[i] - m0v[i] - logf(l0v[i]) + LOGK;
            out[NZ + 1 + gr] = (float)ami[i];        // codes
        }
    }

    // deterministic CTA reductions (fixed tree)
    __syncthreads();
    Ss[tid] = csum;
    __syncthreads();
    for (int st = 128; st > 0; st >>= 1) {
        if (tid < st) Ss[tid] += Ss[tid + st];
        __syncthreads();
    }
    if (tid == 0) g_commitPart[blockIdx.x] = Ss[0];
    __syncthreads();
    Ss[tid] = ksum;
    __syncthreads();
    for (int st = 128; st > 0; st >>= 1) {
        if (tid < st) Ss[tid] += Ss[tid + st];
        __syncthreads();
    }
    if (tid == 0) g_klPart[blockIdx.x] = Ss[0];
}

// ---------------- final deterministic loss reduction ----------------------
__global__ void vq_finish(float* __restrict__ out)
{
    __shared__ float sb[NBLK];
    int t = threadIdx.x;
    sb[t] = g_commitPart[t];
    __syncthreads();
    for (int s = NBLK / 2; s > 0; s >>= 1) {
        if (t < s) sb[t] += sb[t + s];
        __syncthreads();
    }
    float commit = sb[0];
    __syncthreads();
    sb[t] = g_klPart[t];
    __syncthreads();
    for (int s = NBLK / 2; s > 0; s >>= 1) {
        if (t < s) sb[t] += sb[t + s];
        __syncthreads();
    }
    float kl = sb[0];
    if (t == 0)
        out[NZ] = 0.25f * (commit * (1.0f / (float)NZ))
                + 0.01f * (kl * (1.0f / (float)NROWS));
}

extern "C" void kernel_launch(void* const* d_in, const int* in_sizes, int n_in,
                              void* d_out, int out_size)
{
    const float* z  = (const float*)d_in[0];   // (8,64,32,256) fp32
    const float* cb = (const float*)d_in[1];   // (8192,256) fp32
    float* out = (float*)d_out;

    const int smemBytes = (BR * DIM + KT * CS_PITCH + BR * SS_PITCH) * 4; // 148224
    cudaFuncSetAttribute(vq_main, cudaFuncAttributeMaxDynamicSharedMemorySize, smemBytes);

    vq_main<<<NBLK, 256, smemBytes>>>(z, cb, out);
    vq_finish<<<1, NBLK>>>(out);
}